// round 1
// baseline (speedup 1.0000x reference)
#include <cuda_runtime.h>

#define BB      256
#define MAXLEN  10000
#define NATOMS  2000
#define NBONDS  1999
#define NANG    1998
#define NTOR    1997
#define NBT     50
#define NAT     100
#define NTT     200
#define PTOT    (NBT + NAT + NTT)   // 350
#define EPSF    1e-8f

__global__ __launch_bounds__(256)
void energy_kernel(const float* __restrict__ feats,
                   const int*   __restrict__ lengths,
                   const float* __restrict__ opt,
                   const float* __restrict__ btype,
                   const float* __restrict__ atype,
                   const float* __restrict__ ttype,
                   float*       __restrict__ out)
{
    __shared__ float scoord[3 * NATOMS];   // 24000 B
    __shared__ float sopt[PTOT * 3];       // 4200 B
    __shared__ int   smap[PTOT];           // 1400 B
    __shared__ float swarp[8];

    const int b   = blockIdx.x;
    const int tid = threadIdx.x;
    const float* f = feats + (size_t)b * MAXLEN * 9;

    // Stage coords (col 5), params, and type maps into shared
    for (int m = tid; m < 3 * NATOMS; m += blockDim.x)
        scoord[m] = f[m * 9 + 5];
    for (int i = tid; i < PTOT * 3; i += blockDim.x)
        sopt[i] = opt[i];
    for (int i = tid; i < PTOT; i += blockDim.x) {
        float v;
        if      (i < NBT)       v = btype[i];
        else if (i < NBT + NAT) v = atype[i - NBT];
        else                    v = ttype[i - NBT - NAT];
        smap[i] = (int)v;
    }
    __syncthreads();

    const int nb = lengths[b * 9 + 6] / 3;
    const int na = lengths[b * 9 + 7] / 4;
    const int nt = lengths[b * 9 + 8] / 5;

    float acc = 0.0f;

    // ---- bonds: E = k * (r - r0)^2 ----
    for (int t = tid; t < NBONDS; t += blockDim.x) {
        if (t >= nb) continue;
        int i  = (int)f[(3 * t + 0) * 9 + 6];
        int j  = (int)f[(3 * t + 1) * 9 + 6];
        int ty = (int)f[(3 * t + 2) * 9 + 6];
        float dx = scoord[3 * i + 0] - scoord[3 * j + 0];
        float dy = scoord[3 * i + 1] - scoord[3 * j + 1];
        float dz = scoord[3 * i + 2] - scoord[3 * j + 2];
        float r  = sqrtf(dx * dx + dy * dy + dz * dz + EPSF);
        int row  = smap[ty];
        float d  = r - sopt[row * 3 + 1];
        acc += sopt[row * 3 + 0] * d * d;
    }

    // ---- angles: E = k * (theta - theta0)^2 ----
    for (int t = tid; t < NANG; t += blockDim.x) {
        if (t >= na) continue;
        int i  = (int)f[(4 * t + 0) * 9 + 7];
        int j  = (int)f[(4 * t + 1) * 9 + 7];
        int k  = (int)f[(4 * t + 2) * 9 + 7];
        int ty = (int)f[(4 * t + 3) * 9 + 7];
        float ux = scoord[3 * i + 0] - scoord[3 * j + 0];
        float uy = scoord[3 * i + 1] - scoord[3 * j + 1];
        float uz = scoord[3 * i + 2] - scoord[3 * j + 2];
        float vx = scoord[3 * k + 0] - scoord[3 * j + 0];
        float vy = scoord[3 * k + 1] - scoord[3 * j + 1];
        float vz = scoord[3 * k + 2] - scoord[3 * j + 2];
        float duv = ux * vx + uy * vy + uz * vz;
        float duu = ux * ux + uy * uy + uz * uz;
        float dvv = vx * vx + vy * vy + vz * vz;
        float c   = duv * rsqrtf((duu + EPSF) * (dvv + EPSF));
        c = fminf(fmaxf(c, -1.0f + 1e-6f), 1.0f - 1e-6f);
        float theta = acosf(c);
        int row = smap[NBT + ty];
        float d = theta - sopt[row * 3 + 1];
        acc += sopt[row * 3 + 0] * d * d;
    }

    // ---- torsions: E = k * (1 + cos(n*phi - phi0)) ----
    for (int t = tid; t < NTOR; t += blockDim.x) {
        if (t >= nt) continue;
        int i  = (int)f[(5 * t + 0) * 9 + 8];
        int j  = (int)f[(5 * t + 1) * 9 + 8];
        int k  = (int)f[(5 * t + 2) * 9 + 8];
        int l  = (int)f[(5 * t + 3) * 9 + 8];
        int ty = (int)f[(5 * t + 4) * 9 + 8];

        float b1x = scoord[3 * j + 0] - scoord[3 * i + 0];
        float b1y = scoord[3 * j + 1] - scoord[3 * i + 1];
        float b1z = scoord[3 * j + 2] - scoord[3 * i + 2];
        float b2x = scoord[3 * k + 0] - scoord[3 * j + 0];
        float b2y = scoord[3 * k + 1] - scoord[3 * j + 1];
        float b2z = scoord[3 * k + 2] - scoord[3 * j + 2];
        float b3x = scoord[3 * l + 0] - scoord[3 * k + 0];
        float b3y = scoord[3 * l + 1] - scoord[3 * k + 1];
        float b3z = scoord[3 * l + 2] - scoord[3 * k + 2];

        // n1 = b1 x b2 ; n2 = b2 x b3
        float n1x = b1y * b2z - b1z * b2y;
        float n1y = b1z * b2x - b1x * b2z;
        float n1z = b1x * b2y - b1y * b2x;
        float n2x = b2y * b3z - b2z * b3y;
        float n2y = b2z * b3x - b2x * b3z;
        float n2z = b2x * b3y - b2y * b3x;

        float inv = rsqrtf(b2x * b2x + b2y * b2y + b2z * b2z + EPSF);
        float hx = b2x * inv, hy = b2y * inv, hz = b2z * inv;

        // m1 = n1 x b2h
        float m1x = n1y * hz - n1z * hy;
        float m1y = n1z * hx - n1x * hz;
        float m1z = n1x * hy - n1y * hx;

        float sy = m1x * n2x + m1y * n2y + m1z * n2z;
        float sx = n1x * n2x + n1y * n2y + n1z * n2z;
        float phi = atan2f(sy, sx);

        int row = smap[NBT + NAT + ty];
        float kk = sopt[row * 3 + 0];
        float p0 = sopt[row * 3 + 1];
        float mu = sopt[row * 3 + 2];
        acc += kk * (1.0f + cosf(mu * phi - p0));
    }

    // ---- block reduction ----
    #pragma unroll
    for (int off = 16; off > 0; off >>= 1)
        acc += __shfl_down_sync(0xffffffffu, acc, off);
    if ((tid & 31) == 0) swarp[tid >> 5] = acc;
    __syncthreads();
    if (tid < 8) {
        float v = swarp[tid];
        #pragma unroll
        for (int off = 4; off > 0; off >>= 1)
            v += __shfl_down_sync(0xffu, v, off);
        if (tid == 0) out[b] = v;
    }
}

extern "C" void kernel_launch(void* const* d_in, const int* in_sizes, int n_in,
                              void* d_out, int out_size)
{
    const float* feats   = (const float*)d_in[0];
    const int*   lengths = (const int*)  d_in[1];
    const float* opt     = (const float*)d_in[2];
    const float* btype   = (const float*)d_in[3];
    const float* atype   = (const float*)d_in[4];
    const float* ttype   = (const float*)d_in[5];
    float* out = (float*)d_out;

    energy_kernel<<<BB, 256>>>(feats, lengths, opt, btype, atype, ttype, out);
}